// round 14
// baseline (speedup 1.0000x reference)
#include <cuda_runtime.h>
#include <cuda_bf16.h>

// NMU forward: y[b,o] = prod_d ( M_hat[d,o]*x[b,d] + (1 - M_hat[d,o]) )
//            = prod_d ( M_hat[d,o]*(x[b,d]-1) + 1 )
// B=16384, D=256, O=32, fp32.
//
// R14 = R11 (best bucket: 16.86us bench, 40 regs, 3 CTAs/SM, occ 66%) with
// startup-latency polish. Roofline analysis (R5..R13): the fp32 pipe sustains
// 64 lanes/cyc/SM regardless of packing/mix/occupancy -> 28.3K cyc floor;
// this kernel runs ~99% of it, so only overhead trimming remains:
//  - staging x LDGs issued FIRST, weight load/pack overlaps their latency.
//  - row loop unroll 4 for cross-row LDS/math interleave.
//  - otherwise identical to R11: 512 thr, warp owns 16 d's, m2[8] packed,
//    u=x-1 smem, 2 chains, scalar pw, 16-slab epilogue.

#define NMU_D   256
#define NMU_O   32
#define NMU_R   16        // rows per block
#define NMU_NW  16        // warps per block
#define NMU_DPW 16        // d's per warp

#define NMU_ONE2 0x3f8000003f800000ULL

__device__ __forceinline__ unsigned long long f2_fma(unsigned long long a,
                                                     unsigned long long b,
                                                     unsigned long long c) {
    unsigned long long d;
    asm("fma.rn.f32x2 %0, %1, %2, %3;" : "=l"(d) : "l"(a), "l"(b), "l"(c));
    return d;
}
__device__ __forceinline__ unsigned long long f2_mul(unsigned long long a,
                                                     unsigned long long b) {
    unsigned long long d;
    asm("mul.rn.f32x2 %0, %1, %2;" : "=l"(d) : "l"(a), "l"(b));
    return d;
}
__device__ __forceinline__ unsigned long long pack2(float a, float b) {
    unsigned long long d;
    asm("mov.b64 %0, {%1, %2};" : "=l"(d)
        : "r"(__float_as_uint(a)), "r"(__float_as_uint(b)));
    return d;
}
__device__ __forceinline__ float f2_lohi_mul(unsigned long long v) {
    float lo = __uint_as_float((unsigned)(v & 0xffffffffULL));
    float hi = __uint_as_float((unsigned)(v >> 32));
    return lo * hi;
}

__global__ void __launch_bounds__(512, 3)
nmu_kernel(const float* __restrict__ x, const float* __restrict__ M,
           float* __restrict__ out) {
    __shared__ float xs[NMU_R * NMU_D];            // 16 KB (x - 1)
    __shared__ float pw[NMU_NW * NMU_R * NMU_O];   // 32 KB partials

    const int tid  = threadIdx.x;
    const int warp = tid >> 5;
    const int o    = tid & 31;
    const int b0   = blockIdx.x * NMU_R;
    const int d0   = warp * NMU_DPW;

    // --- front-batch staging loads: x LDG.128s issue FIRST ---
    const float4* __restrict__ xg = (const float4*)(x + (size_t)b0 * NMU_D);
    float4 sv0 = __ldg(xg + tid);
    float4 sv1 = __ldg(xg + tid + 512);

    // --- weights (overlap the staging-load latency): 8 packed m-pairs ---
    unsigned long long m2[8];
    {
        const float* __restrict__ Mg = M + (size_t)d0 * NMU_O + o;
        #pragma unroll
        for (int k = 0; k < 8; k++) {
            float a = __saturatef(__ldg(Mg + (2 * k + 0) * NMU_O));
            float b = __saturatef(__ldg(Mg + (2 * k + 1) * NMU_O));
            m2[k] = pack2(a, b);
        }
    }

    // --- finish staging: u = x - 1, conflict-free STS.128 ---
    {
        float4* xs4 = (float4*)xs;
        sv0.x -= 1.0f; sv0.y -= 1.0f; sv0.z -= 1.0f; sv0.w -= 1.0f;
        sv1.x -= 1.0f; sv1.y -= 1.0f; sv1.z -= 1.0f; sv1.w -= 1.0f;
        xs4[tid]       = sv0;
        xs4[tid + 512] = sv1;
    }
    __syncthreads();

    // --- hot loop: 16 rows; 2 chains; unroll 4 for cross-row interleave ---
    #pragma unroll 4
    for (int r = 0; r < NMU_R; r++) {
        const ulonglong2* __restrict__ ur =
            (const ulonglong2*)(xs + r * NMU_D + d0);

        unsigned long long c0, c1;
        {
            ulonglong2 v0 = ur[0], v1 = ur[1];          // d0 .. d0+7
            c0 = f2_fma(m2[0], v0.x, NMU_ONE2);
            c1 = f2_fma(m2[1], v0.y, NMU_ONE2);
            c0 = f2_mul(c0, f2_fma(m2[2], v1.x, NMU_ONE2));
            c1 = f2_mul(c1, f2_fma(m2[3], v1.y, NMU_ONE2));
        }
        {
            ulonglong2 v2 = ur[2], v3 = ur[3];          // d0+8 .. d0+15
            c0 = f2_mul(c0, f2_fma(m2[4], v2.x, NMU_ONE2));
            c1 = f2_mul(c1, f2_fma(m2[5], v2.y, NMU_ONE2));
            c0 = f2_mul(c0, f2_fma(m2[6], v3.x, NMU_ONE2));
            c1 = f2_mul(c1, f2_fma(m2[7], v3.y, NMU_ONE2));
        }

        pw[(warp * NMU_R + r) * NMU_O + o] = f2_lohi_mul(f2_mul(c0, c1));
    }
    __syncthreads();

    // --- epilogue: 1 cell per thread; product over 16 warp slabs ---
    {
        const int row = tid >> 5;            // 0..15
        const int oo  = tid & 31;
        const float* __restrict__ pp = pw + row * NMU_O + oo;
        const int S = NMU_R * NMU_O;         // 512 floats between warp slabs
        float v[8];
        #pragma unroll
        for (int w = 0; w < 8; w++)
            v[w] = pp[(2 * w) * S] * pp[(2 * w + 1) * S];
        float a0 = (v[0] * v[1]) * (v[2] * v[3]);
        float a1 = (v[4] * v[5]) * (v[6] * v[7]);
        out[(size_t)(b0 + row) * NMU_O + oo] = a0 * a1;
    }
}

extern "C" void kernel_launch(void* const* d_in, const int* in_sizes, int n_in,
                              void* d_out, int out_size) {
    const float* x = (const float*)d_in[0];   // [16384, 256]
    const float* M = (const float*)d_in[1];   // [256, 32]
    float* out = (float*)d_out;               // [16384, 32]

    const int B = in_sizes[0] / NMU_D;        // 16384

    nmu_kernel<<<B / NMU_R, 512>>>(x, M, out);
}

// round 15
// speedup vs baseline: 1.0019x; 1.0019x over previous
#include <cuda_runtime.h>
#include <cuda_bf16.h>

// NMU forward: y[b,o] = prod_d ( M_hat[d,o]*x[b,d] + (1 - M_hat[d,o]) )
//            = prod_d ( M_hat[d,o]*(x[b,d]-1) + 1 )
// B=16384, D=256, O=32, fp32.
//
// R15 = R11 (best bench bucket 16.864us; kernel 15.71us; 40 regs, 3 CTAs/SM,
// occ 66%) locked in at the measured fp32 roofline (28.3K cyc: 2 fp32 ops per
// term at 64 lanes/cyc/SM — confirmed invariant across R5..R14), with two
// non-harmful polishes:
//  - full unroll of the 16-row hot loop (no loop branches, max sched window)
//  - streaming stores for the write-once output (st.global.cs)
// Structure: 512 thr (16 warps), warp owns 16 d's, lane = o; m2[8] packed
// (m[d],m[d+1]) pairs; u = x-1 staged d-major in smem (float4 in/out);
// per row 4 bcast LDS.128 + 8 fma2 + 7 mul2 (2 chains) + lohi -> STS.32;
// 16-slab scalar-product epilogue, 1 output/thread.

#define NMU_D   256
#define NMU_O   32
#define NMU_R   16        // rows per block
#define NMU_NW  16        // warps per block
#define NMU_DPW 16        // d's per warp

#define NMU_ONE2 0x3f8000003f800000ULL

__device__ __forceinline__ unsigned long long f2_fma(unsigned long long a,
                                                     unsigned long long b,
                                                     unsigned long long c) {
    unsigned long long d;
    asm("fma.rn.f32x2 %0, %1, %2, %3;" : "=l"(d) : "l"(a), "l"(b), "l"(c));
    return d;
}
__device__ __forceinline__ unsigned long long f2_mul(unsigned long long a,
                                                     unsigned long long b) {
    unsigned long long d;
    asm("mul.rn.f32x2 %0, %1, %2;" : "=l"(d) : "l"(a), "l"(b));
    return d;
}
__device__ __forceinline__ unsigned long long pack2(float a, float b) {
    unsigned long long d;
    asm("mov.b64 %0, {%1, %2};" : "=l"(d)
        : "r"(__float_as_uint(a)), "r"(__float_as_uint(b)));
    return d;
}
__device__ __forceinline__ float f2_lohi_mul(unsigned long long v) {
    float lo = __uint_as_float((unsigned)(v & 0xffffffffULL));
    float hi = __uint_as_float((unsigned)(v >> 32));
    return lo * hi;
}

__global__ void __launch_bounds__(512, 3)
nmu_kernel(const float* __restrict__ x, const float* __restrict__ M,
           float* __restrict__ out) {
    __shared__ float xs[NMU_R * NMU_D];            // 16 KB (x - 1)
    __shared__ float pw[NMU_NW * NMU_R * NMU_O];   // 32 KB partials

    const int tid  = threadIdx.x;
    const int warp = tid >> 5;
    const int o    = tid & 31;
    const int b0   = blockIdx.x * NMU_R;
    const int d0   = warp * NMU_DPW;

    // --- weights: 8 packed m-pairs = 16 registers, loaded once ---
    unsigned long long m2[8];
    {
        const float* __restrict__ Mg = M + (size_t)d0 * NMU_O + o;
        #pragma unroll
        for (int k = 0; k < 8; k++) {
            float a = __saturatef(__ldg(Mg + (2 * k + 0) * NMU_O));
            float b = __saturatef(__ldg(Mg + (2 * k + 1) * NMU_O));
            m2[k] = pack2(a, b);
        }
    }

    // --- stage u = x - 1 (coalesced float4, subtract folded into copy) ---
    {
        const float4* __restrict__ xg = (const float4*)(x + (size_t)b0 * NMU_D);
        float4* xs4 = (float4*)xs;
        #pragma unroll
        for (int i = 0; i < (NMU_R * NMU_D / 4) / 512; i++) {   // 2 iters
            float4 v = __ldg(xg + tid + i * 512);
            v.x -= 1.0f; v.y -= 1.0f; v.z -= 1.0f; v.w -= 1.0f;
            xs4[tid + i * 512] = v;
        }
    }
    __syncthreads();

    // --- hot loop: 16 rows fully unrolled; 2 chains per row ---
    #pragma unroll
    for (int r = 0; r < NMU_R; r++) {
        const ulonglong2* __restrict__ ur =
            (const ulonglong2*)(xs + r * NMU_D + d0);

        unsigned long long c0, c1;
        {
            ulonglong2 v0 = ur[0], v1 = ur[1];          // d0 .. d0+7
            c0 = f2_fma(m2[0], v0.x, NMU_ONE2);
            c1 = f2_fma(m2[1], v0.y, NMU_ONE2);
            c0 = f2_mul(c0, f2_fma(m2[2], v1.x, NMU_ONE2));
            c1 = f2_mul(c1, f2_fma(m2[3], v1.y, NMU_ONE2));
        }
        {
            ulonglong2 v2 = ur[2], v3 = ur[3];          // d0+8 .. d0+15
            c0 = f2_mul(c0, f2_fma(m2[4], v2.x, NMU_ONE2));
            c1 = f2_mul(c1, f2_fma(m2[5], v2.y, NMU_ONE2));
            c0 = f2_mul(c0, f2_fma(m2[6], v3.x, NMU_ONE2));
            c1 = f2_mul(c1, f2_fma(m2[7], v3.y, NMU_ONE2));
        }

        // scalar partial for this (row, warp-chunk, o); conflict-free STS.32
        pw[(warp * NMU_R + r) * NMU_O + o] = f2_lohi_mul(f2_mul(c0, c1));
    }
    __syncthreads();

    // --- epilogue: 1 cell per thread; product over 16 warp slabs ---
    {
        const int row = tid >> 5;            // 0..15
        const int oo  = tid & 31;
        const float* __restrict__ pp = pw + row * NMU_O + oo;
        const int S = NMU_R * NMU_O;         // 512 floats between warp slabs
        float v[8];
        #pragma unroll
        for (int w = 0; w < 8; w++)
            v[w] = pp[(2 * w) * S] * pp[(2 * w + 1) * S];
        float a0 = (v[0] * v[1]) * (v[2] * v[3]);
        float a1 = (v[4] * v[5]) * (v[6] * v[7]);
        float res = a0 * a1;
        // write-once output: streaming store, keep L2 for x/M
        __stcs(out + (size_t)(b0 + row) * NMU_O + oo, res);
    }
}

extern "C" void kernel_launch(void* const* d_in, const int* in_sizes, int n_in,
                              void* d_out, int out_size) {
    const float* x = (const float*)d_in[0];   // [16384, 256]
    const float* M = (const float*)d_in[1];   // [256, 32]
    float* out = (float*)d_out;               // [16384, 32]

    const int B = in_sizes[0] / NMU_D;        // 16384

    nmu_kernel<<<B / NMU_R, 512>>>(x, M, out);
}